// round 3
// baseline (speedup 1.0000x reference)
#include <cuda_runtime.h>
#include <cuda_bf16.h>
#include <math.h>

// Problem constants
#define BB 32
#define TT 512
#define DD 300
#define UU 300
#define ZZ 1200               // 4*U
#define MM (BB*TT)            // 16384
#define NTOT (2*ZZ)           // 2400
#define NT 3                  // output classes

// Recurrent kernel partition
#define RBLK 75               // blocks per direction
#define RUNITS 4              // units per block (75*4 = 300)
#define RTHREADS 256

// -------- persistent device scratch (no allocations allowed) --------
__device__ float g_zx[(size_t)2 * MM * ZZ];      // [dir][row(b*T+t)][z]  157 MB
__device__ float g_hout[(size_t)2 * MM * UU];    // [dir][row][u]         39 MB
__device__ float g_hstate[4 * UU * BB];          // [parity][dir][u*32+b]
__device__ unsigned int g_bar[2];

// ---------------------------------------------------------------
// init: zero h-state (both parities) and barrier counters
// ---------------------------------------------------------------
__global__ void init_kernel() {
    int i = blockIdx.x * blockDim.x + threadIdx.x;
    if (i < 2) g_bar[i] = 0u;
    for (int j = i; j < 4 * UU * BB; j += gridDim.x * blockDim.x)
        g_hstate[j] = 0.0f;
}

// ---------------------------------------------------------------
// zx GEMM: zx[dir][b*T+t][z] = emb[inputs[b,t]] @ Wk_dir + b_dir
// M=16384, N=2400 (cols 0..1199 -> fwd, 1200..2399 -> bwd), K=300
// 128x128x8 tile, 256 threads, 8x8 register tile
// ---------------------------------------------------------------
#define GBM 128
#define GBN 128
#define GBK 8

__global__ void __launch_bounds__(256)
zx_gemm(const int* __restrict__ tokens,
        const float* __restrict__ emb,
        const float* __restrict__ Wkf, const float* __restrict__ Wkb,
        const float* __restrict__ bf,  const float* __restrict__ bb)
{
    __shared__ float As[GBK][GBM];
    __shared__ float Bs[GBK][GBN];

    const int tid = threadIdx.x;
    const int m0 = blockIdx.y * GBM;
    const int n0 = blockIdx.x * GBN;

    // A loader mapping: one float4 per thread per k-tile
    const int a_row = tid >> 1;             // 0..127
    const int a_kq  = (tid & 1) * 4;        // 0 or 4
    const int token = tokens[m0 + a_row];
    const float* arow = emb + (size_t)token * DD;

    // B loader mapping
    const int b_k = tid >> 5;               // 0..7
    const int b_n = (tid & 31) * 4;         // 0..124
    const int ng  = n0 + b_n;
    const int bdir = (ng >= ZZ) ? 1 : 0;
    const float* Wk = bdir ? Wkb : Wkf;
    const int ncol = ng - bdir * ZZ;
    const bool nvalid = (ng < NTOT);

    const int tx = tid & 15;
    const int ty = tid >> 4;

    float acc[8][8];
    #pragma unroll
    for (int i = 0; i < 8; ++i)
        #pragma unroll
        for (int j = 0; j < 8; ++j) acc[i][j] = 0.0f;

    for (int k0 = 0; k0 < DD; k0 += GBK) {
        // load A (gathered embedding rows), zero-pad past K=300
        float4 av = make_float4(0.f, 0.f, 0.f, 0.f);
        {
            int k = k0 + a_kq;
            if (k + 3 < DD) av = *(const float4*)(arow + k);
        }
        As[a_kq + 0][a_row] = av.x;
        As[a_kq + 1][a_row] = av.y;
        As[a_kq + 2][a_row] = av.z;
        As[a_kq + 3][a_row] = av.w;

        // load B
        float4 bv = make_float4(0.f, 0.f, 0.f, 0.f);
        {
            int kb = k0 + b_k;
            if (kb < DD && nvalid)
                bv = *(const float4*)(Wk + (size_t)kb * ZZ + ncol);
        }
        *(float4*)&Bs[b_k][b_n] = bv;

        __syncthreads();

        #pragma unroll
        for (int kk = 0; kk < GBK; ++kk) {
            float4 a0 = *(float4*)&As[kk][ty * 8];
            float4 a1 = *(float4*)&As[kk][ty * 8 + 4];
            float4 b0 = *(float4*)&Bs[kk][tx * 8];
            float4 b1 = *(float4*)&Bs[kk][tx * 8 + 4];
            float af[8] = {a0.x, a0.y, a0.z, a0.w, a1.x, a1.y, a1.z, a1.w};
            float bfr[8] = {b0.x, b0.y, b0.z, b0.w, b1.x, b1.y, b1.z, b1.w};
            #pragma unroll
            for (int i = 0; i < 8; ++i)
                #pragma unroll
                for (int j = 0; j < 8; ++j)
                    acc[i][j] += af[i] * bfr[j];
        }
        __syncthreads();
    }

    // epilogue: add bias, scatter to per-direction zx buffers
    #pragma unroll
    for (int i = 0; i < 8; ++i) {
        int m = m0 + ty * 8 + i;
        #pragma unroll
        for (int j = 0; j < 8; ++j) {
            int n = n0 + tx * 8 + j;
            if (n < NTOT) {
                int dir = (n >= ZZ) ? 1 : 0;
                int zc = n - dir * ZZ;
                float bias = dir ? bb[zc] : bf[zc];
                g_zx[(size_t)dir * MM * ZZ + (size_t)m * ZZ + zc] = acc[i][j] + bias;
            }
        }
    }
}

// ---------------------------------------------------------------
// Persistent recurrent kernel. Grid = 150 blocks (75 per dir),
// 256 threads. Each block owns 4 units x 32 batches x 4 gates.
// Wr slice lives in SMEM for all 512 steps. h exchanged via
// double-buffered global state + per-direction atomic barrier.
// Thread layout: ds = tid>>5 (d-slice 0..7), cell = tid&31:
//   ul = cell>>3 (unit 0..3), bq = cell&7 (batch quad)
// ---------------------------------------------------------------
__device__ __forceinline__ float sigf(float x) {
    return 1.0f / (1.0f + __expf(-x));
}

__global__ void __launch_bounds__(RTHREADS, 2)
lstm_rec(const float* __restrict__ Wrf, const float* __restrict__ Wrb,
         const int* __restrict__ seqlen)
{
    extern __shared__ float smem[];
    float* w_sh  = smem;                    // 300*16 = 4800 floats [d][ul][gate]
    float* h_sh  = smem + 4800;             // 300*32 = 9600 floats [d][b]
    float* red   = smem + 4800 + 9600;      // 8*32*16 = 4096 floats
    float* zx_sh = smem + 4800 + 9600 + 4096; // 32*4*4 = 512 floats [b][gate][ul]

    const int tid  = threadIdx.x;
    const int dir  = blockIdx.x / RBLK;
    const int blk  = blockIdx.x % RBLK;
    const int u0   = blk * RUNITS;

    const float* Wr  = dir ? Wrb : Wrf;
    const float* zxd = g_zx + (size_t)dir * MM * ZZ;

    // fill Wr slice once: w_sh[d*16 + ul*4 + g] = Wr[d][g*300 + u0+ul]
    for (int i = tid; i < DD * 16; i += RTHREADS) {
        int d  = i >> 4;
        int ul = (i >> 2) & 3;
        int gg = i & 3;
        w_sh[i] = Wr[(size_t)d * ZZ + gg * UU + u0 + ul];
    }

    const int ds   = tid >> 5;
    const int cell = tid & 31;
    const int ul   = cell >> 3;
    const int bq   = cell & 7;

    // finisher state (threads 0..127 each own one (b,u) cell)
    float cF = 0.0f, hF = 0.0f;
    int uF = 0, bF = 0, slen = 0;
    if (tid < 128) {
        int cf = tid >> 2, bl = tid & 3;
        uF = u0 + (cf >> 3);
        bF = (cf & 7) * 4 + bl;
        slen = seqlen[bF];
    }
    __syncthreads();

    unsigned int* bar = &g_bar[dir];
    const float4* w4 = (const float4*)w_sh;
    const float4* h4 = (const float4*)h_sh;
    float4* r4  = (float4*)red;
    float4* zs4 = (float4*)zx_sh;

    for (int step = 0; step < TT; ++step) {
        const int t = dir ? (TT - 1 - step) : step;

        // prefetch this step's zx tile (coalesced-ish float4 per (b,gate))
        float4 zv = make_float4(0.f, 0.f, 0.f, 0.f);
        if (tid < 128) {
            int b  = tid >> 2;
            int gg = tid & 3;
            zv = *(const float4*)(zxd + ((size_t)b * TT + t) * ZZ + gg * UU + u0);
        }

        // reload h (written by all blocks of this dir last step) — bypass L1
        {
            const float4* hin =
                (const float4*)(g_hstate + ((step & 1) * 2 + dir) * UU * BB);
            float4* hsh4 = (float4*)h_sh;
            for (int i = tid; i < (UU * BB) / 4; i += RTHREADS)
                hsh4[i] = __ldcg(hin + i);
        }
        __syncthreads();

        // partial dots over d-slice {ds, ds+8, ...}
        float acc[4][4];
        #pragma unroll
        for (int g = 0; g < 4; ++g)
            #pragma unroll
            for (int b = 0; b < 4; ++b) acc[g][b] = 0.0f;

        #pragma unroll 4
        for (int it = 0; it < 37; ++it) {
            int d = ds + it * 8;
            float4 w = w4[d * 4 + ul];
            float4 h = h4[d * 8 + bq];
            acc[0][0] += w.x * h.x; acc[0][1] += w.x * h.y; acc[0][2] += w.x * h.z; acc[0][3] += w.x * h.w;
            acc[1][0] += w.y * h.x; acc[1][1] += w.y * h.y; acc[1][2] += w.y * h.z; acc[1][3] += w.y * h.w;
            acc[2][0] += w.z * h.x; acc[2][1] += w.z * h.y; acc[2][2] += w.z * h.z; acc[2][3] += w.z * h.w;
            acc[3][0] += w.w * h.x; acc[3][1] += w.w * h.y; acc[3][2] += w.w * h.z; acc[3][3] += w.w * h.w;
        }
        if (ds < 4) {
            int d = 296 + ds;
            float4 w = w4[d * 4 + ul];
            float4 h = h4[d * 8 + bq];
            acc[0][0] += w.x * h.x; acc[0][1] += w.x * h.y; acc[0][2] += w.x * h.z; acc[0][3] += w.x * h.w;
            acc[1][0] += w.y * h.x; acc[1][1] += w.y * h.y; acc[1][2] += w.y * h.z; acc[1][3] += w.y * h.w;
            acc[2][0] += w.z * h.x; acc[2][1] += w.z * h.y; acc[2][2] += w.z * h.z; acc[2][3] += w.z * h.w;
            acc[3][0] += w.w * h.x; acc[3][1] += w.w * h.y; acc[3][2] += w.w * h.z; acc[3][3] += w.w * h.w;
        }

        // spill partials + staged zx
        {
            int rb = ds * 128 + cell * 4;   // float4 units
            r4[rb + 0] = make_float4(acc[0][0], acc[0][1], acc[0][2], acc[0][3]);
            r4[rb + 1] = make_float4(acc[1][0], acc[1][1], acc[1][2], acc[1][3]);
            r4[rb + 2] = make_float4(acc[2][0], acc[2][1], acc[2][2], acc[2][3]);
            r4[rb + 3] = make_float4(acc[3][0], acc[3][1], acc[3][2], acc[3][3]);
        }
        if (tid < 128) zs4[tid] = zv;
        __syncthreads();

        // finish: reduce 8 slices, gates, state update, store h
        if (tid < 128) {
            int cf = tid >> 2, bl = tid & 3;
            float zi = zx_sh[(bF * 4 + 0) * 4 + (uF - u0)];
            float zf = zx_sh[(bF * 4 + 1) * 4 + (uF - u0)];
            float zg = zx_sh[(bF * 4 + 2) * 4 + (uF - u0)];
            float zo = zx_sh[(bF * 4 + 3) * 4 + (uF - u0)];
            #pragma unroll
            for (int s = 0; s < 8; ++s) {
                const float* rr = red + s * 512 + cf * 16 + bl;
                zi += rr[0]; zf += rr[4]; zg += rr[8]; zo += rr[12];
            }
            float ig = sigf(zi);
            float fg = sigf(zf);
            float gg = tanhf(zg);
            float og = sigf(zo);
            float cn = fg * cF + ig * gg;
            float hn = og * tanhf(cn);
            if (t < slen) { cF = cn; hF = hn; }
            float* hw = g_hstate + (((step + 1) & 1) * 2 + dir) * UU * BB;
            hw[uF * BB + bF] = hF;
            g_hout[((size_t)dir * MM + (size_t)bF * TT + t) * UU + uF] = hF;
        }

        // per-direction grid barrier (monotonic counter)
        __threadfence();
        __syncthreads();
        if (tid == 0) {
            atomicAdd(bar, 1u);
            unsigned int target = (unsigned int)(step + 1) * RBLK;
            while (atomicAdd(bar, 0u) < target) { }
        }
        __syncthreads();
        __threadfence();
    }
}

// ---------------------------------------------------------------
// Final FC: out[row] = [h_fwd(row) ; h_bwd(row)] @ fc_W + fc_b
// warp per row
// ---------------------------------------------------------------
__global__ void __launch_bounds__(256)
fc_kernel(const float* __restrict__ fcW, const float* __restrict__ fcb,
          float* __restrict__ out)
{
    int gwarp = (blockIdx.x * 256 + threadIdx.x) >> 5;
    int lane  = threadIdx.x & 31;
    // gwarp indexes row = b*T + t ... but g_hout rows for fwd are [dir][b*T+t][u]
    const float* hf = g_hout + (size_t)gwarp * UU;
    const float* hb = g_hout + (size_t)MM * UU + (size_t)gwarp * UU;
    float s0 = 0.f, s1 = 0.f, s2 = 0.f;
    for (int u = lane; u < UU; u += 32) {
        float a = hf[u];
        const float* w = fcW + u * NT;
        s0 += a * w[0]; s1 += a * w[1]; s2 += a * w[2];
        float b = hb[u];
        const float* w2 = fcW + (UU + u) * NT;
        s0 += b * w2[0]; s1 += b * w2[1]; s2 += b * w2[2];
    }
    #pragma unroll
    for (int off = 16; off > 0; off >>= 1) {
        s0 += __shfl_down_sync(0xFFFFFFFFu, s0, off);
        s1 += __shfl_down_sync(0xFFFFFFFFu, s1, off);
        s2 += __shfl_down_sync(0xFFFFFFFFu, s2, off);
    }
    if (lane == 0) {
        out[(size_t)gwarp * NT + 0] = s0 + fcb[0];
        out[(size_t)gwarp * NT + 1] = s1 + fcb[1];
        out[(size_t)gwarp * NT + 2] = s2 + fcb[2];
    }
}

// ---------------------------------------------------------------
extern "C" void kernel_launch(void* const* d_in, const int* in_sizes, int n_in,
                              void* d_out, int out_size)
{
    const int*   tokens = (const int*)  d_in[0];
    const int*   seqlen = (const int*)  d_in[1];
    const float* emb    = (const float*)d_in[2];
    const float* Wkf    = (const float*)d_in[3];
    const float* Wrf    = (const float*)d_in[4];
    const float* bf     = (const float*)d_in[5];
    const float* Wkb    = (const float*)d_in[6];
    const float* Wrb    = (const float*)d_in[7];
    const float* bb     = (const float*)d_in[8];
    const float* fcW    = (const float*)d_in[9];
    const float* fcb    = (const float*)d_in[10];
    float* out = (float*)d_out;

    const int smem_bytes = (4800 + 9600 + 4096 + 512) * 4;  // 76,032 B
    cudaFuncSetAttribute(lstm_rec, cudaFuncAttributeMaxDynamicSharedMemorySize,
                         smem_bytes);

    init_kernel<<<32, 256>>>();
    zx_gemm<<<dim3((NTOT + GBN - 1) / GBN, MM / GBM), 256>>>(tokens, emb, Wkf, Wkb, bf, bb);
    lstm_rec<<<2 * RBLK, RTHREADS, smem_bytes>>>(Wrf, Wrb, seqlen);
    fc_kernel<<<MM / 8, 256>>>(fcW, fcb, out);
}